// round 6
// baseline (speedup 1.0000x reference)
#include <cuda_runtime.h>

#define Bn 8192
#define Dn 256
#define INn 64
#define ONn 256

__device__ float g_innerT[(size_t)Dn * Bn];                 // inner acts, [d][b]
__device__ float g_lutT[Dn * INn];                          // sorted breakpoints
__device__ __align__(16) float2 g_lutSC[Dn * (INn + 1)];    // segment (S, C)

typedef unsigned long long u64;

__device__ __forceinline__ u64 ffma2(u64 a, u64 b, u64 c) {
    u64 d;
    asm("fma.rn.f32x2 %0, %1, %2, %3;" : "=l"(d) : "l"(a), "l"(b), "l"(c));
    return d;
}
__device__ __forceinline__ float2 unpack2(u64 d) {
    float2 r;
    asm("mov.b64 {%0, %1}, %2;" : "=f"(r.x), "=f"(r.y) : "l"(d));
    return r;
}

// ---------------------------------------------------------------------------
// prep: block-per-d rank sort (64 parallel compares, no serial sort chain),
// then scatter + 2-warp shfl scan. 256 blocks x 64 threads.
// ---------------------------------------------------------------------------
__global__ void kan_prep(const float* __restrict__ w1, const float* __restrict__ b1,
                         const float* __restrict__ w2, const float* __restrict__ b2)
{
    const int d = blockIdx.x;
    const int i = threadIdx.x;          // 0..63
    const int lane = i & 31;
    __shared__ float st[64], sS[64], sC[64];
    __shared__ float rs[2], rc[2], tw[2][2];

    const float w = w1[(d << 6) + i];
    const float b = b1[(d << 6) + i];
    const float v = w2[(d << 6) + i];

    float key, dS, dC, bS = 0.f, bC = 0.f;
    if (w == 0.f) {
        key = __int_as_float(0x7f800000); dS = 0.f; dC = 0.f;
        bC = fmaxf(b, 0.f) * v;
    } else {
        key = -b / w;
        const float pS = w * v, pC = b * v;
        if (w > 0.f) { dS = pS;  dC = pC; }
        else         { dS = -pS; dC = -pC; bS = pS; bC = pC; }
    }
    st[i] = key;
    __syncthreads();

    // rank = #(t_j < t_i) + ties broken by index (stable)
    int rank = 0;
    #pragma unroll
    for (int j = 0; j < 64; ++j) {
        const float tj = st[j];
        rank += (tj < key || (tj == key && j < i)) ? 1 : 0;
    }
    __syncthreads();

    // scatter into sorted position; reduce base terms
    st[rank] = key; sS[rank] = dS; sC[rank] = dC;
    float rbS = bS, rbC = bC;
    #pragma unroll
    for (int off = 16; off >= 1; off >>= 1) {
        rbS += __shfl_xor_sync(~0u, rbS, off);
        rbC += __shfl_xor_sync(~0u, rbC, off);
    }
    if (lane == 0) { rs[i >> 5] = rbS; rc[i >> 5] = rbC; }
    __syncthreads();

    // inclusive prefix sums over sorted deltas
    float s = sS[i], c = sC[i];
    #pragma unroll
    for (int off = 1; off < 32; off <<= 1) {
        const float vs = __shfl_up_sync(~0u, s, off);
        const float vc = __shfl_up_sync(~0u, c, off);
        if (lane >= off) { s += vs; c += vc; }
    }
    if (lane == 31) { tw[0][i >> 5] = s; tw[1][i >> 5] = c; }
    __syncthreads();
    if (i >= 32) { s += tw[0][0]; c += tw[1][0]; }

    const float baseS = rs[0] + rs[1];
    const float baseC = rc[0] + rc[1] + __ldg(b2 + d);

    g_lutT[(d << 6) + i] = st[i];
    if (i == 0) g_lutSC[d * 65] = make_float2(baseS, baseC);
    g_lutSC[d * 65 + 1 + i] = make_float2(baseS + s, baseC + c);
}

// ---------------------------------------------------------------------------
// eval: innerT[d][b] = S_p * x[b][d] + C_p via branchless binary search
// ---------------------------------------------------------------------------
__global__ __launch_bounds__(256, 2) void kan_eval(const float* __restrict__ x)
{
    extern __shared__ float sm[];
    float*  sT  = sm;
    float2* sSC = (float2*)(sm + 4096);
    float*  sx  = sm + 4096 + 8320;

    const int b0 = blockIdx.x << 7;
    const int d0 = blockIdx.y << 6;
    const int t  = threadIdx.x;

    {
        const float4* gt = (const float4*)(g_lutT + (d0 << 6));
        const float4* gc = ((const float4*)g_lutSC) + (size_t)(d0 >> 6) * 2080;
        for (int k = t; k < 1024; k += 256) ((float4*)sT)[k] = gt[k];
        for (int k = t; k < 2080; k += 256) ((float4*)sSC)[k] = gc[k];
    }
    for (int k = t; k < 2048; k += 256) {
        const int b = k >> 4, c = (k & 15) << 2;
        float4 v = *(const float4*)(x + (size_t)(b0 + b) * Dn + d0 + c);
        sx[(c + 0) * 129 + b] = v.x;
        sx[(c + 1) * 129 + b] = v.y;
        sx[(c + 2) * 129 + b] = v.z;
        sx[(c + 3) * 129 + b] = v.w;
    }
    __syncthreads();

    const int warp = t >> 5, lane = t & 31;
    #pragma unroll 1
    for (int j = 0; j < 8; ++j) {
        const int dl = (warp << 3) + j;
        const float*  tt = sT + (dl << 6);
        const float2* sc = sSC + dl * 65;
        float* op = g_innerT + (size_t)(d0 + dl) * Bn + b0;
        #pragma unroll
        for (int c = 0; c < 4; ++c) {
            const float xv = sx[dl * 129 + lane + (c << 5)];
            int p = 0;
            p += (tt[31]     <= xv) ? 32 : 0;
            p += (tt[p + 15] <= xv) ? 16 : 0;
            p += (tt[p + 7]  <= xv) ? 8  : 0;
            p += (tt[p + 3]  <= xv) ? 4  : 0;
            p += (tt[p + 1]  <= xv) ? 2  : 0;
            p += (tt[p]      <= xv) ? 1  : 0;
            p += (tt[p]      <= xv) ? 1  : 0;
            const float2 scv = sc[p];
            op[lane + (c << 5)] = fmaf(scv.x, xv, scv.y);
        }
    }
}

// ---------------------------------------------------------------------------
// fused outer MLP, K-paired FFMA2, 256 threads (vs 128: 2x warps/SM for
// latency hiding). btile=32, grid 256, occ 2 -> ~14 warps/SM avg.
// Phase A: 4b x 2i per thread. Phase B: 4b x 4o, 2 passes.
// ---------------------------------------------------------------------------
#define SW_F 17408
#define SIN_F 8192

__global__ __launch_bounds__(256, 2) void kan_fused(
    const float* __restrict__ wo1, const float* __restrict__ bo1,
    const float* __restrict__ wo2, const float* __restrict__ bo2,
    float* __restrict__ out)
{
    extern __shared__ float sm[];
    float* sW  = sm;                      // phase A: wo1 [64][260]; phase B: wo2 [256][68]
    float* sIn = sm + SW_F;               // [32 b][256 k], col k ^ 4*(b>>2)
    float* sG  = sIn + SIN_F;             // [32 b][64 i],  col i ^ 4*(b>>2)

    const int b0 = blockIdx.x << 5;
    const int t  = threadIdx.x;
    const int lo = t & 7;                 // b-quad: b = 4*lo + bb
    const int hi = t >> 3;                // 0..31

    // ---- load wo1 [64][256] -> sW[i][k], stride 260
    for (int idx = t; idx < 4096; idx += 256) {
        const int i = idx >> 6, k4 = (idx & 63) << 2;
        *(float4*)(sW + i * 260 + k4) = *(const float4*)(wo1 + (i << 8) + k4);
    }
    // ---- load inner tile: innerT[d][b0..b0+31] -> sIn[b][d ^ 4*(b>>2)]
    for (int idx = t; idx < 2048; idx += 256) {
        const int dr = idx >> 3, bq = idx & 7;
        const float4 v = *(const float4*)(g_innerT + (size_t)dr * Bn + b0 + (bq << 2));
        const int col = dr ^ (bq << 2);
        sIn[((bq << 2) + 0) * 256 + col] = v.x;
        sIn[((bq << 2) + 1) * 256 + col] = v.y;
        sIn[((bq << 2) + 2) * 256 + col] = v.z;
        sIn[((bq << 2) + 3) * 256 + col] = v.w;
    }
    __syncthreads();

    // ---- Phase A: g[b][i], thread tile 4b x 2i, K=256 paired
    {
        const int i0 = hi << 1;
        u64 acc[4][2];
        #pragma unroll
        for (int bb = 0; bb < 4; ++bb) { acc[bb][0] = 0; acc[bb][1] = 0; }

        const float* pin = sIn + ((lo << 2) << 8);
        const float* pw  = sW + i0 * 260;
        #pragma unroll 2
        for (int k = 0; k < 256; k += 4) {
            const int kx = k ^ (lo << 2);
            ulonglong2 xv[4], wv[2];
            #pragma unroll
            for (int bb = 0; bb < 4; ++bb)
                xv[bb] = *(const ulonglong2*)(pin + (bb << 8) + kx);
            wv[0] = *(const ulonglong2*)(pw + k);
            wv[1] = *(const ulonglong2*)(pw + 260 + k);
            #pragma unroll
            for (int bb = 0; bb < 4; ++bb)
                #pragma unroll
                for (int ii = 0; ii < 2; ++ii) {
                    acc[bb][ii] = ffma2(xv[bb].x, wv[ii].x, acc[bb][ii]);
                    acc[bb][ii] = ffma2(xv[bb].y, wv[ii].y, acc[bb][ii]);
                }
        }
        const float bi0 = __ldg(bo1 + i0);
        const float bi1 = __ldg(bo1 + i0 + 1);
        const int gcol = i0 ^ (lo << 2);
        #pragma unroll
        for (int bb = 0; bb < 4; ++bb) {
            const float2 p0 = unpack2(acc[bb][0]);
            const float2 p1 = unpack2(acc[bb][1]);
            *(float2*)(sG + (((lo << 2) + bb) << 6) + gcol) =
                make_float2(fmaxf(p0.x + p0.y + bi0, 0.f),
                            fmaxf(p1.x + p1.y + bi1, 0.f));
        }
    }
    __syncthreads();

    // ---- load wo2 [256][64] -> sW[o][i], stride 68
    for (int idx = t; idx < 4096; idx += 256) {
        const int o = idx >> 4, i4 = (idx & 15) << 2;
        *(float4*)(sW + o * 68 + i4) = *(const float4*)(wo2 + (o << 6) + i4);
    }
    __syncthreads();

    // ---- Phase B: out[b][o], thread tile 4b x 4o, 2 passes, K=64 paired
    const float* pg = sG + ((lo << 2) << 6);
    #pragma unroll 1
    for (int p = 0; p < 2; ++p) {
        const int o0 = (hi << 2) + (p << 7);
        u64 acc[4][4];
        #pragma unroll
        for (int bb = 0; bb < 4; ++bb)
            #pragma unroll
            for (int oo = 0; oo < 4; ++oo) acc[bb][oo] = 0;

        const float* pw = sW + o0 * 68;
        #pragma unroll 4
        for (int i = 0; i < 64; i += 4) {
            const int ix = i ^ (lo << 2);
            ulonglong2 gv[4], wv[4];
            #pragma unroll
            for (int bb = 0; bb < 4; ++bb)
                gv[bb] = *(const ulonglong2*)(pg + (bb << 6) + ix);
            #pragma unroll
            for (int oo = 0; oo < 4; ++oo)
                wv[oo] = *(const ulonglong2*)(pw + oo * 68 + i);
            #pragma unroll
            for (int bb = 0; bb < 4; ++bb)
                #pragma unroll
                for (int oo = 0; oo < 4; ++oo) {
                    acc[bb][oo] = ffma2(gv[bb].x, wv[oo].x, acc[bb][oo]);
                    acc[bb][oo] = ffma2(gv[bb].y, wv[oo].y, acc[bb][oo]);
                }
        }
        const float4 bv = __ldg((const float4*)(bo2 + o0));
        const float* bvf = (const float*)&bv;
        #pragma unroll
        for (int bb = 0; bb < 4; ++bb) {
            float r[4];
            #pragma unroll
            for (int oo = 0; oo < 4; ++oo) {
                const float2 q = unpack2(acc[bb][oo]);
                r[oo] = q.x + q.y + bvf[oo];
            }
            *(float4*)(out + (size_t)(b0 + (lo << 2) + bb) * ONn + o0) = *(float4*)r;
        }
    }
}

// ---------------------------------------------------------------------------
extern "C" void kernel_launch(void* const* d_in, const int* in_sizes, int n_in,
                              void* d_out, int out_size)
{
    const float* x   = (const float*)d_in[0];
    const float* w1  = (const float*)d_in[1];
    const float* b1  = (const float*)d_in[2];
    const float* w2  = (const float*)d_in[3];
    const float* b2  = (const float*)d_in[4];
    const float* wo1 = (const float*)d_in[5];
    const float* bo1 = (const float*)d_in[6];
    const float* wo2 = (const float*)d_in[7];
    const float* bo2 = (const float*)d_in[8];
    float* out = (float*)d_out;

    const int evalsm  = (4096 + 8320 + 8256) * 4;            // 82688
    const int fusedsm = (SW_F + SIN_F + 2048) * 4;           // 110592
    cudaFuncSetAttribute(kan_eval,  cudaFuncAttributeMaxDynamicSharedMemorySize, evalsm);
    cudaFuncSetAttribute(kan_fused, cudaFuncAttributeMaxDynamicSharedMemorySize, fusedsm);

    kan_prep<<<Dn, 64>>>(w1, b1, w2, b2);
    kan_eval<<<dim3(Bn / 128, Dn / 64), 256, evalsm>>>(x);
    kan_fused<<<Bn / 32, 256, fusedsm>>>(wo1, bo1, wo2, bo2, out);
}

// round 9
// speedup vs baseline: 1.3782x; 1.3782x over previous
#include <cuda_runtime.h>
#include <cuda_bf16.h>
#include <cstdint>

#define Bn 8192
#define Dn 256
#define INn 64
#define ONn 256

typedef unsigned int u32;
typedef unsigned short u16;

// A matrix (inner acts) as packed bf16 pairs: [b][d/2], low half = even d
__device__ __align__(16) u32 g_Ah[(size_t)Bn * (Dn / 2)];   // 4MB
__device__ __align__(16) u32 g_Al[(size_t)Bn * (Dn / 2)];   // 4MB
__device__ float g_lutT[Dn * INn];
__device__ __align__(16) float2 g_lutSC[Dn * (INn + 1)];

__device__ __forceinline__ u32 smem_u32(const void* p) {
    u32 a;
    asm("{ .reg .u64 t; cvta.to.shared.u64 t, %1; cvt.u32.u64 %0, t; }" : "=r"(a) : "l"(p));
    return a;
}
__device__ __forceinline__ void ldm4(u32* r, u32 addr) {
    asm volatile("ldmatrix.sync.aligned.m8n8.x4.shared.b16 {%0,%1,%2,%3}, [%4];"
                 : "=r"(r[0]), "=r"(r[1]), "=r"(r[2]), "=r"(r[3]) : "r"(addr));
}
__device__ __forceinline__ void mma_bf16(float* d, const u32* a, u32 b0, u32 b1) {
    asm volatile("mma.sync.aligned.m16n8k16.row.col.f32.bf16.bf16.f32 "
                 "{%0,%1,%2,%3}, {%4,%5,%6,%7}, {%8,%9}, {%0,%1,%2,%3};"
                 : "+f"(d[0]), "+f"(d[1]), "+f"(d[2]), "+f"(d[3])
                 : "r"(a[0]), "r"(a[1]), "r"(a[2]), "r"(a[3]), "r"(b0), "r"(b1));
}
__device__ __forceinline__ void bsplit(float v, u16& h, u16& l) {
    __nv_bfloat16 hb = __float2bfloat16(v);
    h = __bfloat16_as_ushort(hb);
    l = __bfloat16_as_ushort(__float2bfloat16(v - __bfloat162float(hb)));
}

// ---------------------------------------------------------------------------
// prep: PWL LUT, 4 d per block (rank-sort, no serial chains). grid 64 x 256.
// ---------------------------------------------------------------------------
__global__ void kan_prep(const float* __restrict__ w1, const float* __restrict__ b1,
                         const float* __restrict__ w2, const float* __restrict__ b2)
{
    __shared__ float st[4][64], sS[4][64], sC[4][64];
    __shared__ float rs[4][2], rc[4][2], tws[4][2], twc[4][2];
    const int t = threadIdx.x;
    const int g = t >> 6, i = t & 63, lane = t & 31, half = (t >> 5) & 1;
    const int d = (blockIdx.x << 2) + g;

    const float w = w1[(d << 6) + i];
    const float b = b1[(d << 6) + i];
    const float v = w2[(d << 6) + i];
    float key, dS, dC, bS = 0.f, bC = 0.f;
    if (w == 0.f) {
        key = __int_as_float(0x7f800000); dS = 0.f; dC = 0.f;
        bC = fmaxf(b, 0.f) * v;
    } else {
        key = -b / w;
        const float pS = w * v, pC = b * v;
        if (w > 0.f) { dS = pS;  dC = pC; }
        else         { dS = -pS; dC = -pC; bS = pS; bC = pC; }
    }
    st[g][i] = key;
    __syncthreads();
    int rank = 0;
    #pragma unroll
    for (int j = 0; j < 64; ++j) {
        const float tj = st[g][j];
        rank += (tj < key || (tj == key && j < i)) ? 1 : 0;
    }
    __syncthreads();
    st[g][rank] = key; sS[g][rank] = dS; sC[g][rank] = dC;
    float rbS = bS, rbC = bC;
    #pragma unroll
    for (int off = 16; off >= 1; off >>= 1) {
        rbS += __shfl_xor_sync(~0u, rbS, off);
        rbC += __shfl_xor_sync(~0u, rbC, off);
    }
    if (lane == 0) { rs[g][half] = rbS; rc[g][half] = rbC; }
    __syncthreads();
    float s = sS[g][i], c = sC[g][i];
    #pragma unroll
    for (int off = 1; off < 32; off <<= 1) {
        const float vs = __shfl_up_sync(~0u, s, off);
        const float vc = __shfl_up_sync(~0u, c, off);
        if (lane >= off) { s += vs; c += vc; }
    }
    if (lane == 31) { tws[g][half] = s; twc[g][half] = c; }
    __syncthreads();
    if (half) { s += tws[g][0]; c += twc[g][0]; }
    const float baseS = rs[g][0] + rs[g][1];
    const float baseC = rc[g][0] + rc[g][1] + __ldg(b2 + d);
    g_lutT[(d << 6) + i] = st[g][i];
    if (i == 0) g_lutSC[d * 65] = make_float2(baseS, baseC);
    g_lutSC[d * 65 + 1 + i] = make_float2(baseS + s, baseC + c);
}

// ---------------------------------------------------------------------------
// eval: PWL evaluate + emit A as packed bf16 hi/lo [b][d] (ldmatrix layout).
// In-smem XOR-swizzled transpose stage reuses the sx buffer.
// ---------------------------------------------------------------------------
__global__ __launch_bounds__(256, 2) void kan_eval(const float* __restrict__ x)
{
    extern __shared__ float sm[];
    float*  sT  = sm;                        // [64 d][64]
    float2* sSC = (float2*)(sm + 4096);      // [64 d][65]
    float*  sx  = sm + 4096 + 8320;          // [64 d][129]; later: staging u32[128][64]

    const int b0 = blockIdx.x << 7;
    const int d0 = blockIdx.y << 6;
    const int t  = threadIdx.x;

    {
        const float4* gt = (const float4*)(g_lutT + (d0 << 6));
        const float4* gc = ((const float4*)g_lutSC) + (size_t)(d0 >> 6) * 2080;
        for (int k = t; k < 1024; k += 256) ((float4*)sT)[k] = gt[k];
        for (int k = t; k < 2080; k += 256) ((float4*)sSC)[k] = gc[k];
    }
    for (int k = t; k < 2048; k += 256) {
        const int b = k >> 4, c = (k & 15) << 2;
        float4 v = *(const float4*)(x + (size_t)(b0 + b) * Dn + d0 + c);
        sx[(c + 0) * 129 + b] = v.x;
        sx[(c + 1) * 129 + b] = v.y;
        sx[(c + 2) * 129 + b] = v.z;
        sx[(c + 3) * 129 + b] = v.w;
    }
    __syncthreads();

    const int warp = t >> 5, lane = t & 31;
    float val[8][4];
    #pragma unroll
    for (int j = 0; j < 8; ++j) {
        const int dl = (warp << 3) + j;
        const float*  tt = sT + (dl << 6);
        const float2* sc = sSC + dl * 65;
        #pragma unroll
        for (int c = 0; c < 4; ++c) {
            const float xv = sx[dl * 129 + lane + (c << 5)];
            int p = 0;
            p += (tt[31]     <= xv) ? 32 : 0;
            p += (tt[p + 15] <= xv) ? 16 : 0;
            p += (tt[p + 7]  <= xv) ? 8  : 0;
            p += (tt[p + 3]  <= xv) ? 4  : 0;
            p += (tt[p + 1]  <= xv) ? 2  : 0;
            p += (tt[p]      <= xv) ? 1  : 0;
            p += (tt[p]      <= xv) ? 1  : 0;
            const float2 scv = sc[p];
            val[j][c] = fmaf(scv.x, xv, scv.y);
        }
    }
    __syncthreads();   // all sx reads complete; reuse region as staging

    u32* su = (u32*)sx;  // [128 b][64 dl], col XOR (b & 31)
    #pragma unroll
    for (int j = 0; j < 8; ++j) {
        const int dl = (warp << 3) + j;
        #pragma unroll
        for (int c = 0; c < 4; ++c) {
            const int bl = lane + (c << 5);
            u16 h, l;
            bsplit(val[j][c], h, l);
            su[(bl << 6) + (dl ^ (bl & 31))] = ((u32)h << 16) | l;
        }
    }
    __syncthreads();

    const int d0h = d0 >> 1;
    for (int idx = t; idx < 4096; idx += 256) {
        const int row = idx >> 5, p = idx & 31, f = row & 31;
        const u32 e0 = su[(row << 6) + (((p << 1))     ^ f)];
        const u32 e1 = su[(row << 6) + (((p << 1) | 1) ^ f)];
        const u32 hi = (e0 >> 16) | (e1 & 0xFFFF0000u);
        const u32 lo = (e0 & 0xFFFFu) | (e1 << 16);
        g_Ah[(size_t)(b0 + row) * 128 + d0h + p] = hi;
        g_Al[(size_t)(b0 + row) * 128 + d0h + p] = lo;
    }
}

// ---------------------------------------------------------------------------
// kan_mma: GEMM1 (g = relu(A@wo1^T + bo1), K=256) -> in-register fragment
// conversion -> GEMM2 (out = g@wo2^T + bo2, K=64). bf16 hi/lo corrected.
// grid 128 (btile 64), 128 threads (4 m16 warps), 210KB smem, occ 1.
// ---------------------------------------------------------------------------
#define OF_B1H 0
#define OF_B1L 33792
#define OF_AH  67584
#define OF_AL  101376
#define OF_B2H 135168
#define OF_B2L 172032
#define OF_SB1 208896
#define OF_SB2 209152
#define MMA_SMEM 210176
// pitches (bytes): A,B1 rows = 528 (264 bf16); B2 rows = 144 (72 bf16)

__global__ __launch_bounds__(128, 1) void kan_mma(
    const float* __restrict__ wo1, const float* __restrict__ bo1,
    const float* __restrict__ wo2, const float* __restrict__ bo2,
    float* __restrict__ out)
{
    extern __shared__ char smc[];
    const u32 sb = smem_u32(smc);
    const int t = threadIdx.x;
    const int b0 = blockIdx.x << 6;

    // ---- load + convert wo1 [64][256] -> sB1h/sB1l (bf16, pitch 264)
    for (int idx = t; idx < 4096; idx += 128) {
        const int n = idx >> 6, k4 = (idx & 63) << 2;
        const float4 v = *(const float4*)(wo1 + (n << 8) + k4);
        u16 h[4], l[4];
        bsplit(v.x, h[0], l[0]); bsplit(v.y, h[1], l[1]);
        bsplit(v.z, h[2], l[2]); bsplit(v.w, h[3], l[3]);
        *(ushort4*)(smc + OF_B1H + n * 528 + (k4 << 1)) = make_ushort4(h[0], h[1], h[2], h[3]);
        *(ushort4*)(smc + OF_B1L + n * 528 + (k4 << 1)) = make_ushort4(l[0], l[1], l[2], l[3]);
    }
    // ---- load + convert wo2 [256][64] -> sB2h/sB2l (pitch 72)
    for (int idx = t; idx < 4096; idx += 128) {
        const int o = idx >> 4, i4 = (idx & 15) << 2;
        const float4 v = *(const float4*)(wo2 + (o << 6) + i4);
        u16 h[4], l[4];
        bsplit(v.x, h[0], l[0]); bsplit(v.y, h[1], l[1]);
        bsplit(v.z, h[2], l[2]); bsplit(v.w, h[3], l[3]);
        *(ushort4*)(smc + OF_B2H + o * 144 + (i4 << 1)) = make_ushort4(h[0], h[1], h[2], h[3]);
        *(ushort4*)(smc + OF_B2L + o * 144 + (i4 << 1)) = make_ushort4(l[0], l[1], l[2], l[3]);
    }
    // ---- load A tile rows b0..b0+63 (already bf16-packed) -> sAh/sAl (pitch 264)
    for (int idx = t; idx < 2048; idx += 128) {
        const int b = idx >> 5, c4 = (idx & 31) << 2;
        *(uint4*)(smc + OF_AH + b * 528 + (c4 << 2)) =
            *(const uint4*)(g_Ah + (size_t)(b0 + b) * 128 + c4);
        *(uint4*)(smc + OF_AL + b * 528 + (c4 << 2)) =
            *(const uint4*)(g_Al + (size_t)(b0 + b) * 128 + c4);
    }
    {
        float* sb1 = (float*)(smc + OF_SB1);
        float* sb2 = (float*)(smc + OF_SB2);
        if (t < 64) sb1[t] = __ldg(bo1 + t);
        sb2[t] = __ldg(bo2 + t);
        sb2[t + 128] = __ldg(bo2 + t + 128);
    }
    __syncthreads();

    const int w = t >> 5, lane = t & 31;
    const int m0 = w << 4;
    const int q = lane >> 3, rr = lane & 7;
    const int tq = lane & 3, gg = lane >> 2;

    // ldmatrix lane-role offsets
    const int a_row = m0 + rr + ((q & 1) << 3);          // A: q0/q2 rows g, q1/q3 rows g+8
    const int a_colq = (q >> 1) << 3;                    //    q2/q3 k+8
    const int b_rowq = (q >> 1) << 3;                    // B: q2/q3 = second ntile (n+8)
    const int b_colq = (q & 1) << 3;                     //    q1/q3 k+8

    const u32 aAh = sb + OF_AH + a_row * 528 + (a_colq << 1);
    const u32 aAl = sb + OF_AL + a_row * 528 + (a_colq << 1);

    // ---- GEMM1: D1[8 ntiles][4], K=256 (16 k-steps), 3 passes fused
    float D1[8][4];
    #pragma unroll
    for (int nt = 0; nt < 8; ++nt)
        #pragma unroll
        for (int r = 0; r < 4; ++r) D1[nt][r] = 0.f;

    #pragma unroll 4
    for (int kt = 0; kt < 16; ++kt) {
        u32 ah[4], al[4];
        ldm4(ah, aAh + (kt << 5));
        ldm4(al, aAl + (kt << 5));
        #pragma unroll
        for (int np = 0; np < 4; ++np) {
            const int brow = (np << 4) + rr + b_rowq;
            u32 bh[4], bl[4];
            ldm4(bh, sb + OF_B1H + brow * 528 + (kt << 5) + (b_colq << 1));
            ldm4(bl, sb + OF_B1L + brow * 528 + (kt << 5) + (b_colq << 1));
            mma_bf16(D1[2 * np],     ah, bh[0], bh[1]);
            mma_bf16(D1[2 * np],     al, bh[0], bh[1]);
            mma_bf16(D1[2 * np],     ah, bl[0], bl[1]);
            mma_bf16(D1[2 * np + 1], ah, bh[2], bh[3]);
            mma_bf16(D1[2 * np + 1], al, bh[2], bh[3]);
            mma_bf16(D1[2 * np + 1], ah, bl[2], bl[3]);
        }
    }

    // ---- epilogue 1: relu(D1 + bo1) -> A2 fragments (hi/lo), in registers
    u32 a2h[4][4], a2l[4][4];
    {
        const float* sb1 = (const float*)(smc + OF_SB1);
        #pragma unroll
        for (int nt = 0; nt < 8; ++nt) {
            const float bv0 = sb1[(nt << 3) + (tq << 1)];
            const float bv1 = sb1[(nt << 3) + (tq << 1) + 1];
            const float v0 = fmaxf(D1[nt][0] + bv0, 0.f);
            const float v1 = fmaxf(D1[nt][1] + bv1, 0.f);
            const float v2 = fmaxf(D1[nt][2] + bv0, 0.f);
            const float v3 = fmaxf(D1[nt][3] + bv1, 0.f);
            u16 h0, l0, h1, l1, h2, l2, h3, l3;
            bsplit(v0, h0, l0); bsplit(v1, h1, l1);
            bsplit(v2, h2, l2); bsplit(v3, h3, l3);
            const int j = nt >> 1;
            const int o = (nt & 1) << 1;     // even nt -> a0,a1; odd -> a2,a3
            a2h[j][o]     = (u32)h0 | ((u32)h1 << 16);
            a2h[j][o + 1] = (u32)h2 | ((u32)h3 << 16);
            a2l[j][o]     = (u32)l0 | ((u32)l1 << 16);
            a2l[j][o + 1] = (u32)l2 | ((u32)l3 << 16);
        }
    }

    // ---- GEMM2: out = g @ wo2^T + bo2, K=64 (4 k-steps), N=256 in 2 halves
    const float* sb2 = (const float*)(smc + OF_SB2);
    #pragma unroll 1
    for (int half = 0; half < 2; ++half) {
        float D2[16][4];
        #pragma unroll
        for (int nt = 0; nt < 16; ++nt)
            #pragma unroll
            for (int r = 0; r < 4; ++r) D2[nt][r] = 0.f;

        #pragma unroll
        for (int j = 0; j < 4; ++j) {
            #pragma unroll
            for (int p2 = 0; p2 < 8; ++p2) {
                const int brow = (half << 7) + (p2 << 4) + rr + b_rowq;
                u32 bh[4], bl[4];
                ldm4(bh, sb + OF_B2H + brow * 144 + (j << 5) + (b_colq << 1));
                ldm4(bl, sb + OF_B2L + brow * 144 + (j << 5) + (b_colq << 1));
                mma_bf16(D2[2 * p2],     a2h[j], bh[0], bh[1]);
                mma_bf16(D2[2 * p2],     a2l[j], bh[0], bh[1]);
                mma_bf16(D2[2 * p2],     a2h[j], bl[0], bl[1]);
                mma_bf16(D2[2 * p2 + 1], a2h[j], bh[2], bh[3]);
                mma_bf16(D2[2 * p2 + 1], a2l[j], bh[2], bh[3]);
                mma_bf16(D2[2 * p2 + 1], a2h[j], bl[2], bl[3]);
            }
        }
        // store: c0,c1 -> row g; c2,c3 -> row g+8 (32B-sector coalesced)
        #pragma unroll
        for (int nt = 0; nt < 16; ++nt) {
            const int ob = (half << 7) + (nt << 3);
            const float bv0 = sb2[ob + (tq << 1)];
            const float bv1 = sb2[ob + (tq << 1) + 1];
            const int row = b0 + m0 + gg;
            *(float2*)(out + (size_t)row * ONn + ob + (tq << 1)) =
                make_float2(D2[nt][0] + bv0, D2[nt][1] + bv1);
            *(float2*)(out + (size_t)(row + 8) * ONn + ob + (tq << 1)) =
                make_float2(D2[nt][2] + bv0, D2[nt][3] + bv1);
        }
    }
}

// ---------------------------------------------------------------------------
extern "C" void kernel_launch(void* const* d_in, const int* in_sizes, int n_in,
                              void* d_out, int out_size)
{
    const float* x   = (const float*)d_in[0];
    const float* w1  = (const float*)d_in[1];
    const float* b1  = (const float*)d_in[2];
    const float* w2  = (const float*)d_in[3];
    const float* b2  = (const float*)d_in[4];
    const float* wo1 = (const float*)d_in[5];
    const float* bo1 = (const float*)d_in[6];
    const float* wo2 = (const float*)d_in[7];
    const float* bo2 = (const float*)d_in[8];
    float* out = (float*)d_out;

    const int evalsm = (4096 + 8320 + 8256) * 4;     // 82688
    cudaFuncSetAttribute(kan_eval, cudaFuncAttributeMaxDynamicSharedMemorySize, evalsm);
    cudaFuncSetAttribute(kan_mma,  cudaFuncAttributeMaxDynamicSharedMemorySize, MMA_SMEM);

    kan_prep<<<64, 256>>>(w1, b1, w2, b2);
    kan_eval<<<dim3(Bn / 128, Dn / 64), 256, evalsm>>>(x);
    kan_mma<<<Bn / 64, 128, MMA_SMEM>>>(wo1, bo1, wo2, bo2, out);
}